// round 2
// baseline (speedup 1.0000x reference)
#include <cuda_runtime.h>

#define NUM_EXPERTS 8
#define AUX_COEF 0.02f

// Scratch accumulators (allocation-free per harness rules)
__device__ float g_sum_prob[NUM_EXPERTS];
__device__ float g_cnt[NUM_EXPERTS];

__global__ void router_init_kernel() {
    if (threadIdx.x < NUM_EXPERTS) {
        g_sum_prob[threadIdx.x] = 0.0f;
        g_cnt[threadIdx.x] = 0.0f;
    }
}

__global__ void __launch_bounds__(256) router_main_kernel(
    const float4* __restrict__ in, int num_tokens)
{
    const int tid    = blockIdx.x * blockDim.x + threadIdx.x;
    const int stride = gridDim.x * blockDim.x;

    float sp[NUM_EXPERTS];
    float ct[NUM_EXPERTS];
#pragma unroll
    for (int e = 0; e < NUM_EXPERTS; e++) { sp[e] = 0.0f; ct[e] = 0.0f; }

    for (int t = tid; t < num_tokens; t += stride) {
        // one token row = 32 contiguous bytes: two float4 loads
        float4 a = in[2 * t];
        float4 b = in[2 * t + 1];
        float x[NUM_EXPERTS] = {a.x, a.y, a.z, a.w, b.x, b.y, b.z, b.w};

        // softmax without max-subtraction: logits ~ N(0,1), |x| << 88, no overflow
        float ex[NUM_EXPERTS];
        float s = 0.0f;
#pragma unroll
        for (int e = 0; e < NUM_EXPERTS; e++) {
            ex[e] = __expf(x[e]);
            s += ex[e];
        }
        float inv = __frcp_rn(s);
#pragma unroll
        for (int e = 0; e < NUM_EXPERTS; e++)
            sp[e] = fmaf(ex[e], inv, sp[e]);

        // top-2 indices on logits (softmax is monotone).
        // Ascending scan with strict > matches jax.lax.top_k lowest-index tie-break.
        int i1 = 0;
        float m1 = x[0];
#pragma unroll
        for (int e = 1; e < NUM_EXPERTS; e++) {
            if (x[e] > m1) { m1 = x[e]; i1 = e; }
        }
        int i2 = (i1 == 0) ? 1 : 0;
        float m2 = x[i2];
#pragma unroll
        for (int e = 0; e < NUM_EXPERTS; e++) {
            if (e != i1 && x[e] > m2) { m2 = x[e]; i2 = e; }
        }
#pragma unroll
        for (int e = 0; e < NUM_EXPERTS; e++)
            ct[e] += (e == i1 ? 1.0f : 0.0f) + (e == i2 ? 1.0f : 0.0f);
    }

    // warp reduction
#pragma unroll
    for (int e = 0; e < NUM_EXPERTS; e++) {
#pragma unroll
        for (int off = 16; off > 0; off >>= 1) {
            sp[e] += __shfl_down_sync(0xffffffffu, sp[e], off);
            ct[e] += __shfl_down_sync(0xffffffffu, ct[e], off);
        }
    }

    // block reduction in shared, then one atomic per expert per block
    __shared__ float ssp[NUM_EXPERTS];
    __shared__ float sct[NUM_EXPERTS];
    if (threadIdx.x < NUM_EXPERTS) { ssp[threadIdx.x] = 0.0f; sct[threadIdx.x] = 0.0f; }
    __syncthreads();
    if ((threadIdx.x & 31) == 0) {
#pragma unroll
        for (int e = 0; e < NUM_EXPERTS; e++) {
            atomicAdd(&ssp[e], sp[e]);
            atomicAdd(&sct[e], ct[e]);
        }
    }
    __syncthreads();
    if (threadIdx.x < NUM_EXPERTS) {
        atomicAdd(&g_sum_prob[threadIdx.x], ssp[threadIdx.x]);
        atomicAdd(&g_cnt[threadIdx.x], sct[threadIdx.x]);
    }
}

__global__ void router_final_kernel(float* __restrict__ out, int num_tokens) {
    if (threadIdx.x == 0 && blockIdx.x == 0) {
        double total = 0.0;
        for (int e = 0; e < NUM_EXPERTS; e++)
            total += (double)g_cnt[e] * (double)g_sum_prob[e];
        double T = (double)num_tokens;
        out[0] = (float)((double)AUX_COEF * (double)NUM_EXPERTS * total / (T * T));
    }
}

extern "C" void kernel_launch(void* const* d_in, const int* in_sizes, int n_in,
                              void* d_out, int out_size) {
    const float4* in = (const float4*)d_in[0];
    float* out = (float*)d_out;
    int num_tokens = in_sizes[0] / NUM_EXPERTS;

    router_init_kernel<<<1, 32>>>();
    const int threads = 256;
    const int blocks = 148 * 16;  // 2368 blocks, grid-stride covers 4.19M tokens
    router_main_kernel<<<blocks, threads>>>(in, num_tokens);
    router_final_kernel<<<1, 32>>>(out, num_tokens);
}

// round 3
// speedup vs baseline: 1.1623x; 1.1623x over previous
#include <cuda_runtime.h>

#define E 8
#define NBLK 1184          // 148 SMs * 8
#define NTHR 256
#define NWARP (NTHR / 32)

// Per-block partial results: written (not accumulated) every run -> no init kernel,
// no global atomics, fully deterministic.
__device__ float g_psp[NBLK][E];
__device__ float g_pct[NBLK][E];

__device__ __forceinline__ void process_token(const float4 a, const float4 b,
                                              float* sp, unsigned long long& cnt) {
    float x[E] = {a.x, a.y, a.z, a.w, b.x, b.y, b.z, b.w};

    // softmax terms (logits ~ N(0,1): no overflow without max-subtraction)
    float ex[E];
#pragma unroll
    for (int e = 0; e < E; e++) ex[e] = __expf(x[e]);
    float s = ((ex[0] + ex[1]) + (ex[2] + ex[3])) + ((ex[4] + ex[5]) + (ex[6] + ex[7]));
    float inv;
    asm("rcp.approx.f32 %0, %1;" : "=f"(inv) : "f"(s));
#pragma unroll
    for (int e = 0; e < E; e++) sp[e] = fmaf(ex[e], inv, sp[e]);

    // top-2 indices on logits (softmax monotone). Strict-> ascending scan matches
    // jax.lax.top_k lowest-index tie-break.
    int i1 = 0; float m1 = x[0];
#pragma unroll
    for (int e = 1; e < E; e++) { if (x[e] > m1) { m1 = x[e]; i1 = e; } }
    int i2 = (i1 == 0) ? 1 : 0; float m2 = x[i2];
#pragma unroll
    for (int e = 0; e < E; e++) { if (e != i1 && x[e] > m2) { m2 = x[e]; i2 = e; } }

    // packed 8x8-bit counters: max 14 tokens/thread, each byte +<=1/token -> no overflow
    cnt += (1ull << (8 * i1)) + (1ull << (8 * i2));
}

__global__ void __launch_bounds__(NTHR) router_main_kernel(
    const float4* __restrict__ in, int num_tokens)
{
    const int tid    = blockIdx.x * NTHR + threadIdx.x;
    const int stride = NBLK * NTHR;

    float sp[E];
#pragma unroll
    for (int e = 0; e < E; e++) sp[e] = 0.0f;
    unsigned long long cnt = 0;

    int t = tid;
    // Unrolled-by-4: 8 independent LDG.128 front-batched -> MLP ~8
    for (; t + 3 * stride < num_tokens; t += 4 * stride) {
        const int t1 = t + stride, t2 = t + 2 * stride, t3 = t + 3 * stride;
        float4 a0 = in[2 * t],      b0 = in[2 * t + 1];
        float4 a1 = in[2 * t1],     b1 = in[2 * t1 + 1];
        float4 a2 = in[2 * t2],     b2 = in[2 * t2 + 1];
        float4 a3 = in[2 * t3],     b3 = in[2 * t3 + 1];
        process_token(a0, b0, sp, cnt);
        process_token(a1, b1, sp, cnt);
        process_token(a2, b2, sp, cnt);
        process_token(a3, b3, sp, cnt);
    }
    for (; t < num_tokens; t += stride) {
        float4 a = in[2 * t], b = in[2 * t + 1];
        process_token(a, b, sp, cnt);
    }

    // unpack packed counters to floats
    float ct[E];
#pragma unroll
    for (int e = 0; e < E; e++) ct[e] = (float)((cnt >> (8 * e)) & 0xFFull);

    // warp reduction
#pragma unroll
    for (int e = 0; e < E; e++) {
#pragma unroll
        for (int off = 16; off > 0; off >>= 1) {
            sp[e] += __shfl_down_sync(0xffffffffu, sp[e], off);
            ct[e] += __shfl_down_sync(0xffffffffu, ct[e], off);
        }
    }

    // cross-warp reduction via shared, then write per-block partials
    __shared__ float sred[NWARP][2 * E];
    const int wid = threadIdx.x >> 5, lane = threadIdx.x & 31;
    if (lane == 0) {
#pragma unroll
        for (int e = 0; e < E; e++) { sred[wid][e] = sp[e]; sred[wid][E + e] = ct[e]; }
    }
    __syncthreads();
    if (threadIdx.x < 2 * E) {
        float v = 0.0f;
#pragma unroll
        for (int w = 0; w < NWARP; w++) v += sred[w][threadIdx.x];
        if (threadIdx.x < E) g_psp[blockIdx.x][threadIdx.x]     = v;
        else                 g_pct[blockIdx.x][threadIdx.x - E] = v;
    }
}

__global__ void __launch_bounds__(1024) router_final_kernel(
    float* __restrict__ out, int num_tokens)
{
    __shared__ float s_sp[1024], s_ct[1024];
    const int tid = threadIdx.x;
    const int e   = tid & 7;
    const int idx = tid >> 3;              // 0..127

    float sp = 0.0f, ct = 0.0f;
    for (int b = idx; b < NBLK; b += 128) { // coalesced: e fastest-varying
        sp += g_psp[b][e];
        ct += g_pct[b][e];
    }
    s_sp[tid] = sp; s_ct[tid] = ct;
    __syncthreads();

    // deterministic tree reduction; strides multiple of 8 preserve expert lane
#pragma unroll
    for (int h = 512; h >= 8; h >>= 1) {
        if (tid < h) { s_sp[tid] += s_sp[tid + h]; s_ct[tid] += s_ct[tid + h]; }
        __syncthreads();
    }

    if (tid == 0) {
        double total = 0.0;
#pragma unroll
        for (int k = 0; k < E; k++)
            total += (double)s_ct[k] * (double)s_sp[k];
        double T = (double)num_tokens;
        out[0] = (float)(0.02 * (double)E * total / (T * T));
    }
}

extern "C" void kernel_launch(void* const* d_in, const int* in_sizes, int n_in,
                              void* d_out, int out_size) {
    const float4* in = (const float4*)d_in[0];
    float* out = (float*)d_out;
    int num_tokens = in_sizes[0] / E;

    router_main_kernel<<<NBLK, NTHR>>>(in, num_tokens);
    router_final_kernel<<<1, 1024>>>(out, num_tokens);
}